// round 1
// baseline (speedup 1.0000x reference)
#include <cuda_runtime.h>

// 4-qubit statevector VQC simulator. One thread holds all 16 complex
// amplitudes in registers; everything fully unrolled so CNOTs compile to
// register renames and gate loops to straight-line FMA code.

struct C { float x, y; };

__device__ __forceinline__ C cmul(C a, C b) {
    return C{ a.x * b.x - a.y * b.y, a.x * b.y + a.y * b.x };
}
// acc + a*b
__device__ __forceinline__ C cmad(C a, C b, C acc) {
    return C{ fmaf(a.x, b.x, fmaf(-a.y, b.y, acc.x)),
              fmaf(a.x, b.y, fmaf( a.y, b.x, acc.y)) };
}

// Apply 2x2 gate on the qubit whose bit-stride is ST (qubit n -> ST = 8>>n).
template <int ST>
__device__ __forceinline__ void apply1q(C* s, C g00, C g01, C g10, C g11) {
#pragma unroll
    for (int i = 0; i < 16; i++) {
        if (i & ST) continue;
        C a = s[i], b = s[i | ST];
        C lo = cmul(g00, a); lo = cmad(g01, b, lo);
        C hi = cmul(g10, a); hi = cmad(g11, b, hi);
        s[i] = lo; s[i | ST] = hi;
    }
}

// CNOT: control bit CB, target bit TB. Pure permutation -> register renames.
template <int CB, int TB>
__device__ __forceinline__ void cnot(C* s) {
#pragma unroll
    for (int i = 0; i < 16; i++) {
        if ((i & CB) && !(i & TB)) {
            C t = s[i]; s[i] = s[i | TB]; s[i | TB] = t;
        }
    }
}

// Fused M = RZ(tz) * RY(ty) * RX(tx)
__device__ __forceinline__ void make_rot(float tx, float ty, float tz,
                                         C& g00, C& g01, C& g10, C& g11) {
    float c1, s1, c2, s2, c3, s3;
    __sincosf(0.5f * tx, &s1, &c1);
    __sincosf(0.5f * ty, &s2, &c2);
    __sincosf(0.5f * tz, &s3, &c3);
    // RY*RX
    C m00{ c2 * c1,  s2 * s1 };
    C m01{ -s2 * c1, -c2 * s1 };
    C m10{ s2 * c1,  -c2 * s1 };
    C m11{ c2 * c1,  -s2 * s1 };
    // RZ = diag(e^{-i tz/2}, e^{+i tz/2})
    C e0{ c3, -s3 }, e1{ c3, s3 };
    g00 = cmul(e0, m00); g01 = cmul(e0, m01);
    g10 = cmul(e1, m10); g11 = cmul(e1, m11);
}

__global__ void __launch_bounds__(32, 1)
vqc_kernel(const float* __restrict__ psi,
           const float* __restrict__ ring,
           const float* __restrict__ prx,
           const float* __restrict__ pry,
           const float* __restrict__ prz,
           float* __restrict__ out) {
    if (threadIdx.x != 0) return;

    // ---- Preload everything up front (vectorized, MLP hides DRAM latency) ----
    float4 psi4  = *reinterpret_cast<const float4*>(psi);     // 4 angles
    float4 ring4a = reinterpret_cast<const float4*>(ring)[0]; // ring[0..1]
    float4 ring4b = reinterpret_cast<const float4*>(ring)[1]; // ring[2..3]

    float RX[40], RY[40], RZ[40];
#pragma unroll
    for (int i = 0; i < 10; i++) {
        float4 vx = reinterpret_cast<const float4*>(prx)[i];
        float4 vy = reinterpret_cast<const float4*>(pry)[i];
        float4 vz = reinterpret_cast<const float4*>(prz)[i];
        RX[4*i+0] = vx.x; RX[4*i+1] = vx.y; RX[4*i+2] = vx.z; RX[4*i+3] = vx.w;
        RY[4*i+0] = vy.x; RY[4*i+1] = vy.y; RY[4*i+2] = vy.z; RY[4*i+3] = vy.w;
        RZ[4*i+0] = vz.x; RZ[4*i+1] = vz.y; RZ[4*i+2] = vz.z; RZ[4*i+3] = vz.w;
    }

    float r[4][2] = { { ring4a.x, ring4a.y }, { ring4a.z, ring4a.w },
                      { ring4b.x, ring4b.y }, { ring4b.z, ring4b.w } };

    // ---- Initial product state: amp[i0 i1 i2 i3] = prod_n ring[n][i_n] ----
    C s[16];
#pragma unroll
    for (int i = 0; i < 16; i++) {
        float v = r[0][(i >> 3) & 1] * r[1][(i >> 2) & 1]
                * r[2][(i >> 1) & 1] * r[3][i & 1];
        s[i] = C{ v, 0.0f };
    }

    // ---- Data encoding: RX(psi[n]) ----
    float psia[4] = { psi4.x, psi4.y, psi4.z, psi4.w };
#pragma unroll
    for (int n = 0; n < 4; n++) {
        float c, sn;
        __sincosf(0.5f * psia[n], &sn, &c);
        C g00{ c, 0.f }, g01{ 0.f, -sn }, g10{ 0.f, -sn }, g11{ c, 0.f };
        if (n == 0)      apply1q<8>(s, g00, g01, g10, g11);
        else if (n == 1) apply1q<4>(s, g00, g01, g10, g11);
        else if (n == 2) apply1q<2>(s, g00, g01, g10, g11);
        else             apply1q<1>(s, g00, g01, g10, g11);
    }

    // ---- Variational layers ----
#pragma unroll
    for (int d = 0; d < 10; d++) {
        // CNOT ring: (0,1),(1,2),(2,3),(3,0) — bit for qubit n is 8>>n
        cnot<8, 4>(s);
        cnot<4, 2>(s);
        cnot<2, 1>(s);
        cnot<1, 8>(s);
        // Fused RZ*RY*RX per qubit (RX applied first, matching reference)
#pragma unroll
        for (int n = 0; n < 4; n++) {
            C g00, g01, g10, g11;
            make_rot(RX[d*4+n], RY[d*4+n], RZ[d*4+n], g00, g01, g10, g11);
            if (n == 0)      apply1q<8>(s, g00, g01, g10, g11);
            else if (n == 1) apply1q<4>(s, g00, g01, g10, g11);
            else if (n == 2) apply1q<2>(s, g00, g01, g10, g11);
            else             apply1q<1>(s, g00, g01, g10, g11);
        }
    }

    // ---- Outputs: |k[0000]|^2, |k[0010]|^2, |k[1111]|^2 ----
    out[0] = s[0].x  * s[0].x  + s[0].y  * s[0].y;
    out[1] = s[2].x  * s[2].x  + s[2].y  * s[2].y;
    out[2] = s[15].x * s[15].x + s[15].y * s[15].y;
}

extern "C" void kernel_launch(void* const* d_in, const int* in_sizes, int n_in,
                              void* d_out, int out_size) {
    const float* psi  = (const float*)d_in[0];
    const float* ring = (const float*)d_in[1];
    const float* prx  = (const float*)d_in[2];
    const float* pry  = (const float*)d_in[3];
    const float* prz  = (const float*)d_in[4];
    float* out = (float*)d_out;
    vqc_kernel<<<1, 32>>>(psi, ring, prx, pry, prz, out);
}

// round 2
// speedup vs baseline: 1.8977x; 1.8977x over previous
#include <cuda_runtime.h>

// 4-qubit statevector VQC, one warp. Lane l (mod 16) holds amplitude index l
// (qubit n <-> bit (8>>n)). Gates are applied via warp shuffles; the 4 ring
// CNOTs per layer are a pure index permutation composed once and fused into
// the qubit-0 gate's (variable-source) shuffle. All trig is computed up front,
// vectorized across lanes (each sincos instruction evaluates 32 angles), and
// staged in shared memory so gate-matrix construction is off the amplitude
// dependency chain.

__global__ void __launch_bounds__(32, 1)
vqc_kernel(const float* __restrict__ psi,
           const float* __restrict__ ring,
           const float* __restrict__ prx,
           const float* __restrict__ pry,
           const float* __restrict__ prz,
           float* __restrict__ out) {
    __shared__ float cosv[128], sinv[128];
    const unsigned FULL = 0xFFFFFFFFu;
    const int l = threadIdx.x;

    // ---- ring init vectors (broadcast loads) ----
    float4 rA = reinterpret_cast<const float4*>(ring)[0];
    float4 rB = reinterpret_cast<const float4*>(ring)[1];

    // ---- vectorized trig: 124 angles, 4 per lane ----
    // angle index a: [0,40)=RX, [40,80)=RY, [80,120)=RZ, [120,124)=psi
#pragma unroll
    for (int t = 0; t < 4; t++) {
        int idx = l + t * 32;
        if (idx < 124) {
            float a;
            if (idx < 40)       a = prx[idx];
            else if (idx < 80)  a = pry[idx - 40];
            else if (idx < 120) a = prz[idx - 80];
            else                a = psi[idx - 120];
            float s, c;
            __sincosf(0.5f * a, &s, &c);
            cosv[idx] = c; sinv[idx] = s;
        }
    }
    __syncwarp();

    // ---- initial product state ----
    float r0[2] = { rA.x, rA.y }, r1[2] = { rA.z, rA.w };
    float r2[2] = { rB.x, rB.y }, r3[2] = { rB.z, rB.w };
    float re = r0[(l >> 3) & 1] * r1[(l >> 2) & 1]
             * r2[(l >> 1) & 1] * r3[l & 1];
    float im = 0.0f;

    // per-lane sign per qubit: -1 if this lane's bit for qubit n is set
    float sb[4];
#pragma unroll
    for (int n = 0; n < 4; n++) sb[n] = (l & (8 >> n)) ? -1.0f : 1.0f;

    // ---- compose the 4 ring CNOTs into one permutation ----
    // CNOT(CB,TB): new[i] = old[(i&CB) ? i^TB : i]; applied in order
    // (8,4),(4,2),(2,1),(1,8) => src = s1(s2(s3(s4(i)))).
    auto perm = [](int j) {
        j = (j & 1) ? (j ^ 8) : j;   // sigma4: CB=1, TB=8
        j = (j & 2) ? (j ^ 1) : j;   // sigma3: CB=2, TB=1
        j = (j & 4) ? (j ^ 2) : j;   // sigma2: CB=4, TB=2
        j = (j & 8) ? (j ^ 4) : j;   // sigma1: CB=8, TB=4
        return j;
    };
    const int src_self = perm(l);
    const int src_part = perm(l ^ 8);

    // ---- data encoding: RX(psi[n]) (bit-independent coefficients) ----
#pragma unroll
    for (int n = 0; n < 4; n++) {
        float c = cosv[120 + n], s = sinv[120 + n];
        float pre = __shfl_xor_sync(FULL, re, 8 >> n);
        float pim = __shfl_xor_sync(FULL, im, 8 >> n);
        float nre = fmaf(c, re,  s * pim);
        float nim = fmaf(c, im, -s * pre);
        re = nre; im = nim;
    }

    // ---- variational layers ----
#pragma unroll
    for (int d = 0; d < 10; d++) {
#pragma unroll
        for (int n = 0; n < 4; n++) {
            // fused M = RZ*RY*RX: only g00,g01 needed;
            // g11 = conj(g00), g10 = -conj(g01) -> per-lane sign sb[n].
            int i = d * 4 + n;
            float c1 = cosv[i],      s1 = sinv[i];
            float c2 = cosv[40 + i], s2 = sinv[40 + i];
            float c3 = cosv[80 + i], s3 = sinv[80 + i];
            float p1 = c2 * c1, p2 = s2 * s1, p3 = s2 * c1, p4 = c2 * s1;
            float g00re =  fmaf(c3, p1,  s3 * p2);
            float g00im =  fmaf(c3, p2, -s3 * p1);
            float g01re = -fmaf(c3, p3,  s3 * p4);
            float g01im =  fmaf(s3, p3, -c3 * p4);
            float Pim = sb[n] * g00im;   // P = lane-bit ? g11 : g00
            float Qre = sb[n] * g01re;   // Q = lane-bit ? g10 : g01 (Qim = g01im)

            float ore, oim, pre, pim;
            if (n == 0) {
                // fuse the 4 CNOTs (permutation) into this gate's shuffles
                ore = __shfl_sync(FULL, re, src_self);
                oim = __shfl_sync(FULL, im, src_self);
                pre = __shfl_sync(FULL, re, src_part);
                pim = __shfl_sync(FULL, im, src_part);
            } else {
                ore = re; oim = im;
                pre = __shfl_xor_sync(FULL, re, 8 >> n);
                pim = __shfl_xor_sync(FULL, im, 8 >> n);
            }

            // new = P*own + Q*partner (complex)
            float nre = g00re * ore;
            nre = fmaf(-Pim,   oim, nre);
            nre = fmaf( Qre,   pre, nre);
            nre = fmaf(-g01im, pim, nre);
            float nim = g00re * oim;
            nim = fmaf( Pim,   ore, nim);
            nim = fmaf( Qre,   pim, nim);
            nim = fmaf( g01im, pre, nim);
            re = nre; im = nim;
        }
    }

    // ---- outputs: |amp[0]|^2, |amp[2]|^2, |amp[15]|^2 ----
    float prob = fmaf(re, re, im * im);
    if (l == 0)       out[0] = prob;
    else if (l == 2)  out[1] = prob;
    else if (l == 15) out[2] = prob;
}

extern "C" void kernel_launch(void* const* d_in, const int* in_sizes, int n_in,
                              void* d_out, int out_size) {
    const float* psi  = (const float*)d_in[0];
    const float* ring = (const float*)d_in[1];
    const float* prx  = (const float*)d_in[2];
    const float* pry  = (const float*)d_in[3];
    const float* prz  = (const float*)d_in[4];
    vqc_kernel<<<1, 32>>>(psi, ring, prx, pry, prz, (float*)d_out);
}